// round 14
// baseline (speedup 1.0000x reference)
#include <cuda_runtime.h>
#include <cuda_bf16.h>

// SepConv: out[b,c,i,j] = sum_{u,v} img[b,c,i+u,j+v] * vert[b,u,i,j] * hori[b,v,i,j]
// Shapes: img[8,3,512,512], hori[8,13,500,500], vert[8,13,500,500], out[8,3,500,500]
// Factorized: out = sum_u vert[u] * (sum_v hori[v] * img[i+u, j+v])
// R11: R9 skeleton (best: 85.8us) + explicit cross-unit window double-buffer.
//   The 39 (u,c) units are flattened; each unit prefetches the NEXT unit's
//   4 LDS.128 window into the alternate buffer before running its own 56-FMA
//   chains, hiding the 29-cy LDS latency under guaranteed fma-busy cycles.

#define KSZ 13
#define CC  3
#define WW  512
#define HH  512
#define WO  500
#define HO  500

#define TX  32                 // thread-groups in j; each thread covers 4 j
#define TY  8                  // output rows per block
#define JBLK (TX * 4)          // 128 output columns per block
#define TILE_ROWS (TY + KSZ - 1)   // 20 img rows
#define TILE_Q   36                // float4 per tile row (144 floats)

#define NUNIT (KSZ * CC)       // 39 flattened (u,c) units

__global__ __launch_bounds__(TX * TY, 2)
void sepconv_kernel(const float* __restrict__ img,
                    const float* __restrict__ hori,
                    const float* __restrict__ vert,
                    float* __restrict__ out) {
    __shared__ float4 s[CC][TILE_ROWS][TILE_Q];

    const int b  = blockIdx.z;
    const int j0 = blockIdx.x * JBLK;
    const int i0 = blockIdx.y * TY;
    const int tx = threadIdx.x, ty = threadIdx.y;
    const int tid = ty * TX + tx;

    const int i = i0 + ty;
    const int j = j0 + 4 * tx;
    const bool active = (i < WO) && (j < HO);    // HO%4==0 -> float4 valid when j<HO
    // clamped coords so edge threads issue harmless in-bounds loads
    const int ic = (i < WO) ? i : (WO - 1);
    const int jc = (j < HO) ? j : (HO - 4);

    // ---- weight loads FIRST: independent of smem, overlap the tile load ----
    float4 hw[KSZ];
    const float* hbase = hori + (((size_t)b * KSZ) * WO + ic) * HO + jc;
    #pragma unroll
    for (int v = 0; v < KSZ; v++)
        hw[v] = *(const float4*)(hbase + (size_t)v * WO * HO);

    const float* vbase = vert + (((size_t)b * KSZ) * WO + ic) * HO + jc;
    float4 vw_next = *(const float4*)(vbase);

    // ---- cooperative load of the img tile (3 channels, 20 rows, 144 cols) ----
    const int NQ = CC * TILE_ROWS * TILE_Q;   // 2160 float4
    for (int f = tid; f < NQ; f += TX * TY) {
        int c   = f / (TILE_ROWS * TILE_Q);
        int rem = f - c * (TILE_ROWS * TILE_Q);
        int r   = rem / TILE_Q;
        int q   = rem - r * TILE_Q;
        int gx  = i0 + r; if (gx > WW - 1) gx = WW - 1;   // clamped rows feed only invalid outs
        int gy  = j0 + 4 * q;
        const float* base = img + (((size_t)b * CC + c) * WW + gx) * HH;
        float4 val;
        if (gy + 3 <= HH - 1) {
            val = *(const float4*)(base + gy);
        } else {
            int y0 = gy     < HH ? gy     : HH - 1;
            int y1 = gy + 1 < HH ? gy + 1 : HH - 1;
            int y2 = gy + 2 < HH ? gy + 2 : HH - 1;
            int y3 = gy + 3 < HH ? gy + 3 : HH - 1;
            val = make_float4(base[y0], base[y1], base[y2], base[y3]);
        }
        s[c][r][q] = val;
    }
    __syncthreads();

    if (!active) return;   // no further barriers below

    float4 acc[CC];
    #pragma unroll
    for (int c = 0; c < CC; c++) acc[c] = make_float4(0.f, 0.f, 0.f, 0.f);

    // ---- flattened (u,c) mainloop with window double-buffer ----
    float4 wb[2][4];
    {   // preload unit 0 (u=0, c=0)
        const float4* rp = &s[0][ty][0] + tx;
        wb[0][0] = rp[0]; wb[0][1] = rp[1]; wb[0][2] = rp[2]; wb[0][3] = rp[3];
    }
    float4 vw = vw_next;   // vw for u=0
    vw_next = *(const float4*)(vbase + (size_t)1 * WO * HO);

    #pragma unroll
    for (int t = 0; t < NUNIT; t++) {
        const int u = t / CC;
        const int c = t % CC;

        // prefetch next unit's window into the alternate slot
        if (t + 1 < NUNIT) {
            const int u2 = (t + 1) / CC;
            const int c2 = (t + 1) % CC;
            const float4* rp = &s[c2][ty + u2][0] + tx;
            wb[(t + 1) & 1][0] = rp[0];
            wb[(t + 1) & 1][1] = rp[1];
            wb[(t + 1) & 1][2] = rp[2];
            wb[(t + 1) & 1][3] = rp[3];
        }
        // rotate vw at each new u (c==0), prefetching one u ahead
        if (c == 0 && t > 0) {
            vw = vw_next;
            if (u + 1 < KSZ)
                vw_next = *(const float4*)(vbase + (size_t)(u + 1) * WO * HO);
        }

        const float4 t0 = wb[t & 1][0], t1 = wb[t & 1][1];
        const float4 t2 = wb[t & 1][2], t3 = wb[t & 1][3];
        const float w[16] = { t0.x, t0.y, t0.z, t0.w,  t1.x, t1.y, t1.z, t1.w,
                              t2.x, t2.y, t2.z, t2.w,  t3.x, t3.y, t3.z, t3.w };
        float r0 = 0.f, r1 = 0.f, r2 = 0.f, r3 = 0.f;
        #pragma unroll
        for (int v = 0; v < KSZ; v++) {
            r0 = fmaf(hw[v].x, w[v + 0], r0);
            r1 = fmaf(hw[v].y, w[v + 1], r1);
            r2 = fmaf(hw[v].z, w[v + 2], r2);
            r3 = fmaf(hw[v].w, w[v + 3], r3);
        }
        acc[c].x = fmaf(vw.x, r0, acc[c].x);
        acc[c].y = fmaf(vw.y, r1, acc[c].y);
        acc[c].z = fmaf(vw.z, r2, acc[c].z);
        acc[c].w = fmaf(vw.w, r3, acc[c].w);
    }

    #pragma unroll
    for (int c = 0; c < CC; c++) {
        float* obase = out + (((size_t)b * CC + c) * WO + i) * HO + j;
        *(float4*)obase = acc[c];
    }
}

extern "C" void kernel_launch(void* const* d_in, const int* in_sizes, int n_in,
                              void* d_out, int out_size) {
    const float* img  = (const float*)d_in[0];
    const float* hori = (const float*)d_in[1];
    const float* vert = (const float*)d_in[2];
    float* out = (float*)d_out;

    const int B = 8;
    dim3 block(TX, TY);                     // 256 threads
    dim3 grid((HO + JBLK - 1) / JBLK,       // 4
              (WO + TY - 1) / TY,           // 63
              B);                           // 8 -> 2016 blocks
    sepconv_kernel<<<grid, block>>>(img, hori, vert, out);
}

// round 15
// speedup vs baseline: 1.2303x; 1.2303x over previous
#include <cuda_runtime.h>
#include <cuda_bf16.h>

// SepConv: out[b,c,i,j] = sum_{u,v} img[b,c,i+u,j+v] * vert[b,u,i,j] * hori[b,v,i,j]
// Shapes: img[8,3,512,512], hori[8,13,500,500], vert[8,13,500,500], out[8,3,500,500]
// Factorized: out = sum_u vert[u] * (sum_v hori[v] * img[i+u, j+v])
// R12: persistent CTAs (grid = 2*numSM) + cp.async double-buffered img tiles.
//   Each CTA loops over ~7 tiles; while computing tile t from buffer p, the
//   cp.async engine fills buffer p^1 with tile t+grid. The wait_group+barrier
//   lands AFTER ~4.5k cycles of FMA, so the tile load latency (the per-tile
//   serial prologue that R9 paid synchronously) is fully hidden.
//   Compute body is byte-for-byte the proven R9 inner loop.

#define KSZ 13
#define CC  3
#define WW  512
#define HH  512
#define WO  500
#define HO  500

#define TX  32                     // j-groups; each thread covers 4 j
#define TY  8                      // output rows per tile
#define JBLK (TX * 4)              // 128 output columns per tile
#define TILE_ROWS (TY + KSZ - 1)   // 20 img rows
#define TILE_Q   36                // float4 per tile row
#define TILE_F4 (CC * TILE_ROWS * TILE_Q)   // 2160 float4 per tile buffer
#define NTILE (4 * 63 * 8)         // 2016 tiles
#define SMEM_BYTES (2 * TILE_F4 * 16)       // 69120 B

__device__ __forceinline__ void cp16(float4* s, const float4* g) {
    unsigned a = (unsigned)__cvta_generic_to_shared(s);
    asm volatile("cp.async.cg.shared.global [%0], [%1], 16;" :: "r"(a), "l"(g));
}

// Issue cp.async loads for tile t into dst (no wait). Skips OOB float4s:
//  - rows gx>=512 feed only outputs i>=500 (never stored)
//  - cols gy>=512 (gy is a multiple of 4, so either gy+3<=511 or fully OOB)
//    are only read by window positions of outputs j>=500 (never stored)
__device__ __forceinline__ void issue_tile(const float* __restrict__ img,
                                           int t, float4* dst, int tid) {
    const int jb   = t & 3;
    const int rest = t >> 2;
    const int ib   = rest % 63;
    const int b    = rest / 63;
    const int i0 = ib * TY, j0 = jb * JBLK;
    for (int f = tid; f < TILE_F4; f += TX * TY) {
        int c   = f / (TILE_ROWS * TILE_Q);
        int rem = f - c * (TILE_ROWS * TILE_Q);
        int r   = rem / TILE_Q;
        int q   = rem - r * TILE_Q;
        int gx  = i0 + r;
        int gy  = j0 + 4 * q;
        if (gx < WW && gy <= HH - 4)
            cp16(dst + f, (const float4*)(img + (((size_t)b * CC + c) * WW + gx) * HH + gy));
    }
    asm volatile("cp.async.commit_group;");
}

__global__ __launch_bounds__(TX * TY, 2)
void sepconv_kernel(const float* __restrict__ img,
                    const float* __restrict__ hori,
                    const float* __restrict__ vert,
                    float* __restrict__ out,
                    int grid) {
    extern __shared__ float4 sb[];          // [2][TILE_F4]

    const int tid = threadIdx.x;
    const int tx  = tid & 31;
    const int ty  = tid >> 5;

    int t = blockIdx.x;
    if (t >= NTILE) return;
    int p = 0;
    issue_tile(img, t, sb, tid);            // preload first tile into buf 0

    for (; t < NTILE; t += grid) {
        asm volatile("cp.async.wait_group 0;");
        __syncthreads();                    // buf p full; prior reads of buf p^1 done

        // ---- decode tile ----
        const int jb   = t & 3;
        const int rest = t >> 2;
        const int ib   = rest % 63;
        const int b    = rest / 63;
        const int i0 = ib * TY, j0 = jb * JBLK;
        const int i = i0 + ty;
        const int j = j0 + 4 * tx;
        const bool active = (i < WO) && (j < HO);
        const int ic = (i < WO) ? i : (WO - 1);
        const int jc = (j < HO) ? j : (HO - 4);

        // ---- weight loads (issued first; ride under cp.async issue + warm-up) ----
        float4 hw[KSZ];
        const float* hbase = hori + (((size_t)b * KSZ) * WO + ic) * HO + jc;
        #pragma unroll
        for (int v = 0; v < KSZ; v++)
            hw[v] = *(const float4*)(hbase + (size_t)v * WO * HO);

        const float* vbase = vert + (((size_t)b * KSZ) * WO + ic) * HO + jc;
        float4 vw_next = *(const float4*)(vbase);

        // ---- prefetch next tile into the alternate buffer (async, no wait) ----
        const int tn = t + grid;
        if (tn < NTILE)
            issue_tile(img, tn, sb + (p ^ 1) * TILE_F4, tid);

        // ---- compute tile t from buf p (R9 body) ----
        const float4* s = sb + p * TILE_F4;

        float4 acc[CC];
        #pragma unroll
        for (int c = 0; c < CC; c++) acc[c] = make_float4(0.f, 0.f, 0.f, 0.f);

        #pragma unroll
        for (int u = 0; u < KSZ; u++) {
            float4 vw = vw_next;
            if (u + 1 < KSZ)
                vw_next = *(const float4*)(vbase + (size_t)(u + 1) * WO * HO);

            #pragma unroll
            for (int c = 0; c < CC; c++) {
                const float4* row4 = s + (c * TILE_ROWS + ty + u) * TILE_Q + tx;
                float w[16];
                #pragma unroll
                for (int k = 0; k < 4; k++) {
                    float4 t4 = row4[k];
                    w[4*k+0] = t4.x; w[4*k+1] = t4.y; w[4*k+2] = t4.z; w[4*k+3] = t4.w;
                }
                float r0 = 0.f, r1 = 0.f, r2 = 0.f, r3 = 0.f;
                #pragma unroll
                for (int v = 0; v < KSZ; v++) {
                    r0 = fmaf(hw[v].x, w[v + 0], r0);
                    r1 = fmaf(hw[v].y, w[v + 1], r1);
                    r2 = fmaf(hw[v].z, w[v + 2], r2);
                    r3 = fmaf(hw[v].w, w[v + 3], r3);
                }
                acc[c].x = fmaf(vw.x, r0, acc[c].x);
                acc[c].y = fmaf(vw.y, r1, acc[c].y);
                acc[c].z = fmaf(vw.z, r2, acc[c].z);
                acc[c].w = fmaf(vw.w, r3, acc[c].w);
            }
        }

        if (active) {
            #pragma unroll
            for (int c = 0; c < CC; c++) {
                float* obase = out + (((size_t)b * CC + c) * WO + i) * HO + j;
                *(float4*)obase = acc[c];
            }
        }
        p ^= 1;
    }
}

extern "C" void kernel_launch(void* const* d_in, const int* in_sizes, int n_in,
                              void* d_out, int out_size) {
    const float* img  = (const float*)d_in[0];
    const float* hori = (const float*)d_in[1];
    const float* vert = (const float*)d_in[2];
    float* out = (float*)d_out;

    cudaFuncSetAttribute(sepconv_kernel,
                         cudaFuncAttributeMaxDynamicSharedMemorySize, SMEM_BYTES);

    int dev = 0;
    cudaGetDevice(&dev);
    int sms = 148;
    cudaDeviceGetAttribute(&sms, cudaDevAttrMultiProcessorCount, dev);
    int grid = 2 * sms;
    if (grid > NTILE) grid = NTILE;

    sepconv_kernel<<<grid, TX * TY, SMEM_BYTES>>>(img, hori, vert, out, grid);
}